// round 2
// baseline (speedup 1.0000x reference)
#include <cuda_runtime.h>
#include <math.h>
#include <math_constants.h>

#define NMAX 100000
#define EMAX 1600000
#define D 128
#define NHEAD 4

// ---------------- static scratch (allowed: __device__ globals) ----------------
__device__ float g_h[(size_t)NMAX * D];        // transformed features [N,128]
__device__ float g_asrc[NMAX * NHEAD];         // per-node src attention term
__device__ float g_adst[NMAX * NHEAD];         // per-node dst attention term
__device__ int   g_src[EMAX];
__device__ int   g_dst[EMAX];
__device__ int   g_deg[NMAX];
__device__ int   g_off[NMAX];
__device__ int   g_cur[NMAX];
__device__ int   g_csr[EMAX];                  // src node per incoming edge, grouped by dst
__device__ int   g_is64;

// ---------------- dtype detection for edge_index (int64 vs int32) ----------------
__global__ void k_detect(const void* ei) {
    const unsigned int* w = (const unsigned int*)ei;
    int all0 = 1;
    #pragma unroll
    for (int k = 0; k < 64; k++)
        if (w[2 * k + 1] != 0u) all0 = 0;
    g_is64 = all0;  // values < 2^31 and nonneg -> high word zero iff int64
}

__global__ void k_zero_deg(int n) {
    int i = blockIdx.x * blockDim.x + threadIdx.x;
    if (i < n) g_deg[i] = 0;
}

__global__ void k_extract(const void* ei, int E) {
    int i = blockIdx.x * blockDim.x + threadIdx.x;
    if (i >= E) return;
    int s, d;
    if (g_is64) {
        const long long* p = (const long long*)ei;
        s = (int)p[i]; d = (int)p[E + i];
    } else {
        const int* p = (const int*)ei;
        s = p[i]; d = p[E + i];
    }
    g_src[i] = s; g_dst[i] = d;
    atomicAdd(&g_deg[d], 1);
}

// single-block exclusive scan of degrees -> offsets (+ cursor copy)
__global__ void k_scan(int n) {
    __shared__ int sm[1024];
    int tid = threadIdx.x;
    int chunk = (n + 1023) >> 10;
    int b = tid * chunk;
    int e = min(b + chunk, n);
    int s = 0;
    for (int i = b; i < e; i++) s += g_deg[i];
    sm[tid] = s;
    __syncthreads();
    for (int off = 1; off < 1024; off <<= 1) {
        int v = (tid >= off) ? sm[tid - off] : 0;
        __syncthreads();
        sm[tid] += v;
        __syncthreads();
    }
    int excl = (tid == 0) ? 0 : sm[tid - 1];
    for (int i = b; i < e; i++) {
        g_off[i] = excl; g_cur[i] = excl;
        excl += g_deg[i];
    }
}

__global__ void k_scatter(int E) {
    int i = blockIdx.x * blockDim.x + threadIdx.x;
    if (i >= E) return;
    int d = g_dst[i];
    int pos = atomicAdd(&g_cur[d], 1);
    g_csr[pos] = g_src[i];
}

// ---------------- GEMM: h = x @ W (fp32), fused attention dots ----------------
// block: 256 threads, tile 64 rows x 128 cols, K tiled by 64 (48KB static smem)
__global__ void k_gemm(const float* __restrict__ x, const float* __restrict__ W,
                       const float* __restrict__ att_src, const float* __restrict__ att_dst,
                       int n) {
    __shared__ float ws[64 * 128];   // 32KB: W[kt*64 .. +63][0..127]
    __shared__ float xs[64 * 64];    // 16KB: x[r0 .. +63][kt*64 .. +63]
    int tid = threadIdx.x;
    int r0 = blockIdx.x * 64;
    int w = tid >> 5;          // warp -> rows w*8..w*8+7
    int l = tid & 31;          // lane -> cols 4l..4l+3

    float acc[8][4];
    #pragma unroll
    for (int i = 0; i < 8; i++) { acc[i][0]=0.f; acc[i][1]=0.f; acc[i][2]=0.f; acc[i][3]=0.f; }

    for (int kt = 0; kt < 2; kt++) {
        // load W rows kt*64..+63  (2048 float4)
        for (int i = tid; i < 2048; i += 256)
            ((float4*)ws)[i] = ((const float4*)W)[(kt * 64) * 32 + i];
        // load x tile (1024 float4): row r, float4-col c4 in [0,16)
        for (int i = tid; i < 1024; i += 256) {
            int r = i >> 4, c4 = i & 15;
            float4 v = make_float4(0.f, 0.f, 0.f, 0.f);
            if (r0 + r < n) v = ((const float4*)x)[(size_t)(r0 + r) * 32 + kt * 16 + c4];
            ((float4*)xs)[i] = v;
        }
        __syncthreads();
        const float* xrow = xs + w * 8 * 64;
        #pragma unroll 4
        for (int k = 0; k < 64; k++) {
            float4 wv = ((float4*)(ws + k * 128))[l];
            #pragma unroll
            for (int i = 0; i < 8; i++) {
                float xv = xrow[i * 64 + k];   // broadcast within warp
                acc[i][0] += xv * wv.x; acc[i][1] += xv * wv.y;
                acc[i][2] += xv * wv.z; acc[i][3] += xv * wv.w;
            }
        }
        __syncthreads();
    }

    float4 asv = __ldg(((const float4*)att_src) + l);  // att flattened [H*C]=[128]
    float4 adv = __ldg(((const float4*)att_dst) + l);
    int head = l >> 3;
    #pragma unroll
    for (int i = 0; i < 8; i++) {
        int r = r0 + w * 8 + i;
        if (r < n) {   // uniform per warp
            ((float4*)(g_h + (size_t)r * D))[l] =
                make_float4(acc[i][0], acc[i][1], acc[i][2], acc[i][3]);
            float ps = acc[i][0]*asv.x + acc[i][1]*asv.y + acc[i][2]*asv.z + acc[i][3]*asv.w;
            float pd = acc[i][0]*adv.x + acc[i][1]*adv.y + acc[i][2]*adv.z + acc[i][3]*adv.w;
            #pragma unroll
            for (int o = 1; o < 8; o <<= 1) {
                ps += __shfl_xor_sync(0xffffffffu, ps, o);
                pd += __shfl_xor_sync(0xffffffffu, pd, o);
            }
            if ((l & 7) == 0) {
                g_asrc[r * NHEAD + head] = ps;
                g_adst[r * NHEAD + head] = pd;
            }
        }
    }
}

// online-softmax combine with -inf guard
__device__ __forceinline__ void comb(float& m1, float& s1, float m2, float s2) {
    if (m2 > m1) { float t = m1; m1 = m2; m2 = t; t = s1; s1 = s2; s2 = t; }
    if (m2 != -CUDART_INF_F) s1 += s2 * __expf(m2 - m1);
}

// ---------------- fused per-node: softmax + aggregate + LN + PReLU + residual ----
__global__ void k_node(const float* __restrict__ x, const float* __restrict__ bias,
                       const float* __restrict__ gamma, const float* __restrict__ beta,
                       const float* __restrict__ prelu_w, float* __restrict__ out, int n) {
    int node = blockIdx.x;
    int tid = threadIdx.x;              // 128 threads = 128 channels
    int lane = tid & 31, warp = tid >> 5;
    int hh = tid >> 5;                  // head of this channel

    __shared__ float alpha_s[128 * 4];
    __shared__ int   src_s[128];
    __shared__ float adsh[4];
    __shared__ float redm[4][4], reds[4][4];  // [warp][head]
    __shared__ float sm_m[4], sm_is[4];
    __shared__ float rsum[4], rsq[4];
    __shared__ float sm_mu, sm_rs;

    int beg = g_off[node];
    int deg = g_deg[node];

    if (tid < 4) adsh[tid] = g_adst[node * NHEAD + tid];
    __syncthreads();
    float ad0 = adsh[0], ad1 = adsh[1], ad2 = adsh[2], ad3 = adsh[3];

    // pass 1: online softmax stats per head
    float m[4] = {-CUDART_INF_F, -CUDART_INF_F, -CUDART_INF_F, -CUDART_INF_F};
    float ss[4] = {0.f, 0.f, 0.f, 0.f};
    for (int i = tid; i < deg; i += 128) {
        int s = g_csr[beg + i];
        float4 av = __ldg((const float4*)(g_asrc + s * NHEAD));
        float l0 = av.x + ad0; l0 = l0 >= 0.f ? l0 : 0.2f * l0;
        float l1 = av.y + ad1; l1 = l1 >= 0.f ? l1 : 0.2f * l1;
        float l2 = av.z + ad2; l2 = l2 >= 0.f ? l2 : 0.2f * l2;
        float l3 = av.w + ad3; l3 = l3 >= 0.f ? l3 : 0.2f * l3;
        float lv[4] = {l0, l1, l2, l3};
        #pragma unroll
        for (int h = 0; h < 4; h++) {
            float l = lv[h];
            if (l > m[h]) { ss[h] = ss[h] * __expf(m[h] - l) + 1.f; m[h] = l; }
            else          { ss[h] += __expf(l - m[h]); }
        }
    }
    #pragma unroll
    for (int o = 16; o > 0; o >>= 1) {
        #pragma unroll
        for (int h = 0; h < 4; h++) {
            float mo = __shfl_down_sync(0xffffffffu, m[h], o);
            float so = __shfl_down_sync(0xffffffffu, ss[h], o);
            comb(m[h], ss[h], mo, so);
        }
    }
    if (lane == 0) {
        #pragma unroll
        for (int h = 0; h < 4; h++) { redm[warp][h] = m[h]; reds[warp][h] = ss[h]; }
    }
    __syncthreads();
    if (tid == 0) {
        #pragma unroll
        for (int h = 0; h < 4; h++) {
            float mm = redm[0][h], sv = reds[0][h];
            comb(mm, sv, redm[1][h], reds[1][h]);
            comb(mm, sv, redm[2][h], reds[2][h]);
            comb(mm, sv, redm[3][h], reds[3][h]);
            sm_m[h] = mm;
            sm_is[h] = 1.f / (sv + 1e-16f);
        }
    }
    __syncthreads();
    float mh0 = sm_m[0], mh1 = sm_m[1], mh2 = sm_m[2], mh3 = sm_m[3];
    float is0 = sm_is[0], is1 = sm_is[1], is2 = sm_is[2], is3 = sm_is[3];

    // pass 2: chunked alpha + coalesced gather-accumulate
    float acc = 0.f;
    for (int base = 0; base < deg; base += 128) {
        int cn = min(128, deg - base);
        if (tid < cn) {
            int s = g_csr[beg + base + tid];
            float4 av = __ldg((const float4*)(g_asrc + s * NHEAD));
            float l0 = av.x + ad0; l0 = l0 >= 0.f ? l0 : 0.2f * l0;
            float l1 = av.y + ad1; l1 = l1 >= 0.f ? l1 : 0.2f * l1;
            float l2 = av.z + ad2; l2 = l2 >= 0.f ? l2 : 0.2f * l2;
            float l3 = av.w + ad3; l3 = l3 >= 0.f ? l3 : 0.2f * l3;
            float4 al;
            al.x = __expf(l0 - mh0) * is0;
            al.y = __expf(l1 - mh1) * is1;
            al.z = __expf(l2 - mh2) * is2;
            al.w = __expf(l3 - mh3) * is3;
            ((float4*)alpha_s)[tid] = al;
            src_s[tid] = s;
        }
        __syncthreads();
        #pragma unroll 4
        for (int j = 0; j < cn; j++) {
            int s = src_s[j];                      // smem broadcast
            float a = alpha_s[j * 4 + hh];         // smem broadcast
            acc += a * __ldg(&g_h[(size_t)s * D + tid]);  // coalesced 128B/warp
        }
        __syncthreads();
    }

    // LayerNorm + PReLU + residual
    float v = acc + __ldg(&bias[tid]);
    float s1 = v, s2 = v * v;
    #pragma unroll
    for (int o = 16; o > 0; o >>= 1) {
        s1 += __shfl_xor_sync(0xffffffffu, s1, o);
        s2 += __shfl_xor_sync(0xffffffffu, s2, o);
    }
    if (lane == 0) { rsum[warp] = s1; rsq[warp] = s2; }
    __syncthreads();
    if (tid == 0) {
        float S1 = rsum[0] + rsum[1] + rsum[2] + rsum[3];
        float S2 = rsq[0] + rsq[1] + rsq[2] + rsq[3];
        float mu = S1 * (1.f / 128.f);
        float var = fmaxf(S2 * (1.f / 128.f) - mu * mu, 0.f);
        sm_mu = mu;
        sm_rs = rsqrtf(var + 1e-5f);
    }
    __syncthreads();
    float o = (v - sm_mu) * sm_rs * __ldg(&gamma[tid]) + __ldg(&beta[tid]);
    float pw = __ldg(prelu_w);
    o = o >= 0.f ? o : pw * o;
    out[(size_t)node * D + tid] = o + __ldg(&x[(size_t)node * D + tid]);
}

// ---------------- launch ----------------
extern "C" void kernel_launch(void* const* d_in, const int* in_sizes, int n_in,
                              void* d_out, int out_size) {
    const float* x       = (const float*)d_in[0];
    const void*  ei      = d_in[1];
    const float* W       = (const float*)d_in[2];
    const float* att_src = (const float*)d_in[3];
    const float* att_dst = (const float*)d_in[4];
    const float* bias    = (const float*)d_in[5];
    const float* gamma   = (const float*)d_in[6];
    const float* beta    = (const float*)d_in[7];
    const float* prelu   = (const float*)d_in[8];
    float* out = (float*)d_out;

    int n = in_sizes[0] / D;
    int E = in_sizes[1] / 2;

    k_detect<<<1, 1>>>(ei);
    k_zero_deg<<<(n + 255) / 256, 256>>>(n);
    k_extract<<<(E + 255) / 256, 256>>>(ei, E);
    k_scan<<<1, 1024>>>(n);
    k_scatter<<<(E + 255) / 256, 256>>>(E);
    k_gemm<<<(n + 63) / 64, 256>>>(x, W, att_src, att_dst, n);
    k_node<<<n, 128>>>(x, bias, gamma, beta, prelu, out, n);
}

// round 5
// speedup vs baseline: 1.3271x; 1.3271x over previous
#include <cuda_runtime.h>
#include <math.h>
#include <math_constants.h>

#define NMAX 100000
#define EMAX 1600000
#define D 128
#define NHEAD 4

// ---------------- static scratch (allowed: __device__ globals) ----------------
__device__ float g_h[(size_t)NMAX * D];        // transformed features [N,128]
__device__ float g_asrc[NMAX * NHEAD];         // per-node src attention term
__device__ float g_adst[NMAX * NHEAD];         // per-node dst attention term
__device__ int   g_src[EMAX];
__device__ int   g_dst[EMAX];
__device__ int   g_rank[EMAX];                 // arrival rank among edges sharing dst
__device__ int   g_deg[NMAX];
__device__ int   g_off[NMAX];
__device__ int   g_csr[EMAX];                  // src node per incoming edge, grouped by dst
__device__ int   g_bsum[1024];                 // per-block degree sums for scan
__device__ int   g_is64;

// ---------------- dtype detection for edge_index (int64 vs int32) ----------------
__global__ void k_detect(const void* ei) {
    const unsigned int* w = (const unsigned int*)ei;
    int all0 = 1;
    #pragma unroll
    for (int k = 0; k < 64; k++)
        if (w[2 * k + 1] != 0u) all0 = 0;
    g_is64 = all0;  // values < 2^31 and nonneg -> high word zero iff int64
}

__global__ void k_zero_deg(int n) {
    int i = blockIdx.x * blockDim.x + threadIdx.x;
    if (i < n) g_deg[i] = 0;
}

// extract src/dst, count degree, remember per-edge rank (removes 2nd atomic pass)
__global__ void k_extract(const void* ei, int E) {
    int i = blockIdx.x * blockDim.x + threadIdx.x;
    if (i >= E) return;
    int s, d;
    if (g_is64) {
        const long long* p = (const long long*)ei;
        s = (int)p[i]; d = (int)p[E + i];
    } else {
        const int* p = (const int*)ei;
        s = p[i]; d = p[E + i];
    }
    g_src[i] = s; g_dst[i] = d;
    g_rank[i] = atomicAdd(&g_deg[d], 1);
}

// ---------------- hierarchical exclusive scan of degrees ----------------
// pass 1: per-block (1024-wide) exclusive scan, write local offsets + block sum
__global__ void k_scan1(int n) {
    __shared__ int wsum[32];
    int tid = threadIdx.x;
    int gid = blockIdx.x * 1024 + tid;
    int v = (gid < n) ? g_deg[gid] : 0;
    int lane = tid & 31, wid = tid >> 5;
    int xv = v;
    #pragma unroll
    for (int o = 1; o < 32; o <<= 1) {
        int t = __shfl_up_sync(0xffffffffu, xv, o);
        if (lane >= o) xv += t;
    }
    if (lane == 31) wsum[wid] = xv;
    __syncthreads();
    if (wid == 0) {
        int s = wsum[lane];
        #pragma unroll
        for (int o = 1; o < 32; o <<= 1) {
            int t = __shfl_up_sync(0xffffffffu, s, o);
            if (lane >= o) s += t;
        }
        wsum[lane] = s;
    }
    __syncthreads();
    int incl = xv + (wid ? wsum[wid - 1] : 0);
    if (gid < n) g_off[gid] = incl - v;          // block-local exclusive
    if (tid == 1023) g_bsum[blockIdx.x] = incl;  // block total
}

// pass 2: single-block exclusive scan of block sums (B <= 1024)
__global__ void k_scan2(int B) {
    __shared__ int wsum[32];
    int tid = threadIdx.x;
    int v = (tid < B) ? g_bsum[tid] : 0;
    int lane = tid & 31, wid = tid >> 5;
    int xv = v;
    #pragma unroll
    for (int o = 1; o < 32; o <<= 1) {
        int t = __shfl_up_sync(0xffffffffu, xv, o);
        if (lane >= o) xv += t;
    }
    if (lane == 31) wsum[wid] = xv;
    __syncthreads();
    if (wid == 0) {
        int s = wsum[lane];
        #pragma unroll
        for (int o = 1; o < 32; o <<= 1) {
            int t = __shfl_up_sync(0xffffffffu, s, o);
            if (lane >= o) s += t;
        }
        wsum[lane] = s;
    }
    __syncthreads();
    int incl = xv + (wid ? wsum[wid - 1] : 0);
    if (tid < B) g_bsum[tid] = incl - v;         // exclusive block prefix
}

// pass 3: add block prefix -> final global offsets
__global__ void k_scan3(int n) {
    int gid = blockIdx.x * 1024 + threadIdx.x;
    if (gid < n) g_off[gid] += g_bsum[blockIdx.x];
}

// atomic-free scatter using precomputed ranks
__global__ void k_scatter(int E) {
    int i = blockIdx.x * blockDim.x + threadIdx.x;
    if (i >= E) return;
    g_csr[g_off[g_dst[i]] + g_rank[i]] = g_src[i];
}

// ---------------- GEMM: h = x @ W (fp32), fused attention dots ----------------
// block: 256 threads, tile 64 rows x 128 cols, K tiled by 64 (48KB static smem)
__global__ void k_gemm(const float* __restrict__ x, const float* __restrict__ W,
                       const float* __restrict__ att_src, const float* __restrict__ att_dst,
                       int n) {
    __shared__ float ws[64 * 128];   // 32KB: W[kt*64 .. +63][0..127]
    __shared__ float xs[64 * 64];    // 16KB: x[r0 .. +63][kt*64 .. +63]
    int tid = threadIdx.x;
    int r0 = blockIdx.x * 64;
    int w = tid >> 5;          // warp -> rows w*8..w*8+7
    int l = tid & 31;          // lane -> cols 4l..4l+3

    float acc[8][4];
    #pragma unroll
    for (int i = 0; i < 8; i++) { acc[i][0]=0.f; acc[i][1]=0.f; acc[i][2]=0.f; acc[i][3]=0.f; }

    for (int kt = 0; kt < 2; kt++) {
        for (int i = tid; i < 2048; i += 256)
            ((float4*)ws)[i] = ((const float4*)W)[(kt * 64) * 32 + i];
        for (int i = tid; i < 1024; i += 256) {
            int r = i >> 4, c4 = i & 15;
            float4 v = make_float4(0.f, 0.f, 0.f, 0.f);
            if (r0 + r < n) v = ((const float4*)x)[(size_t)(r0 + r) * 32 + kt * 16 + c4];
            ((float4*)xs)[i] = v;
        }
        __syncthreads();
        const float* xrow = xs + w * 8 * 64;
        #pragma unroll 4
        for (int k = 0; k < 64; k++) {
            float4 wv = ((float4*)(ws + k * 128))[l];
            #pragma unroll
            for (int i = 0; i < 8; i++) {
                float xv = xrow[i * 64 + k];
                acc[i][0] += xv * wv.x; acc[i][1] += xv * wv.y;
                acc[i][2] += xv * wv.z; acc[i][3] += xv * wv.w;
            }
        }
        __syncthreads();
    }

    float4 asv = __ldg(((const float4*)att_src) + l);
    float4 adv = __ldg(((const float4*)att_dst) + l);
    int head = l >> 3;
    #pragma unroll
    for (int i = 0; i < 8; i++) {
        int r = r0 + w * 8 + i;
        if (r < n) {
            ((float4*)(g_h + (size_t)r * D))[l] =
                make_float4(acc[i][0], acc[i][1], acc[i][2], acc[i][3]);
            float ps = acc[i][0]*asv.x + acc[i][1]*asv.y + acc[i][2]*asv.z + acc[i][3]*asv.w;
            float pd = acc[i][0]*adv.x + acc[i][1]*adv.y + acc[i][2]*adv.z + acc[i][3]*adv.w;
            #pragma unroll
            for (int o = 1; o < 8; o <<= 1) {
                ps += __shfl_xor_sync(0xffffffffu, ps, o);
                pd += __shfl_xor_sync(0xffffffffu, pd, o);
            }
            if ((l & 7) == 0) {
                g_asrc[r * NHEAD + head] = ps;
                g_adst[r * NHEAD + head] = pd;
            }
        }
    }
}

// online-softmax combine with -inf guard
__device__ __forceinline__ void comb(float& m1, float& s1, float m2, float s2) {
    if (m2 > m1) { float t = m1; m1 = m2; m2 = t; t = s1; s1 = s2; s2 = t; }
    if (m2 != -CUDART_INF_F) s1 += s2 * __expf(m2 - m1);
}

// ---------------- fused per-node: softmax + aggregate + LN + PReLU + residual ----
__global__ void k_node(const float* __restrict__ x, const float* __restrict__ bias,
                       const float* __restrict__ gamma, const float* __restrict__ beta,
                       const float* __restrict__ prelu_w, float* __restrict__ out, int n) {
    int node = blockIdx.x;
    int tid = threadIdx.x;              // 128 threads = 128 channels
    int lane = tid & 31, warp = tid >> 5;
    int hh = tid >> 5;                  // head of this channel

    __shared__ float alpha_s[128 * 4];
    __shared__ int   src_s[128];
    __shared__ float adsh[4];
    __shared__ float redm[4][4], reds[4][4];
    __shared__ float sm_m[4], sm_is[4];
    __shared__ float rsum[4], rsq[4];
    __shared__ float sm_mu, sm_rs;

    int beg = g_off[node];
    int deg = g_deg[node];

    if (tid < 4) adsh[tid] = g_adst[node * NHEAD + tid];
    __syncthreads();
    float ad0 = adsh[0], ad1 = adsh[1], ad2 = adsh[2], ad3 = adsh[3];

    // pass 1: online softmax stats per head
    float m[4] = {-CUDART_INF_F, -CUDART_INF_F, -CUDART_INF_F, -CUDART_INF_F};
    float ss[4] = {0.f, 0.f, 0.f, 0.f};
    for (int i = tid; i < deg; i += 128) {
        int s = g_csr[beg + i];
        float4 av = __ldg((const float4*)(g_asrc + s * NHEAD));
        float l0 = av.x + ad0; l0 = l0 >= 0.f ? l0 : 0.2f * l0;
        float l1 = av.y + ad1; l1 = l1 >= 0.f ? l1 : 0.2f * l1;
        float l2 = av.z + ad2; l2 = l2 >= 0.f ? l2 : 0.2f * l2;
        float l3 = av.w + ad3; l3 = l3 >= 0.f ? l3 : 0.2f * l3;
        float lv[4] = {l0, l1, l2, l3};
        #pragma unroll
        for (int h = 0; h < 4; h++) {
            float l = lv[h];
            if (l > m[h]) { ss[h] = ss[h] * __expf(m[h] - l) + 1.f; m[h] = l; }
            else          { ss[h] += __expf(l - m[h]); }
        }
    }
    #pragma unroll
    for (int o = 16; o > 0; o >>= 1) {
        #pragma unroll
        for (int h = 0; h < 4; h++) {
            float mo = __shfl_down_sync(0xffffffffu, m[h], o);
            float so = __shfl_down_sync(0xffffffffu, ss[h], o);
            comb(m[h], ss[h], mo, so);
        }
    }
    if (lane == 0) {
        #pragma unroll
        for (int h = 0; h < 4; h++) { redm[warp][h] = m[h]; reds[warp][h] = ss[h]; }
    }
    __syncthreads();
    if (tid == 0) {
        #pragma unroll
        for (int h = 0; h < 4; h++) {
            float mm = redm[0][h], sv = reds[0][h];
            comb(mm, sv, redm[1][h], reds[1][h]);
            comb(mm, sv, redm[2][h], reds[2][h]);
            comb(mm, sv, redm[3][h], reds[3][h]);
            sm_m[h] = mm;
            sm_is[h] = 1.f / (sv + 1e-16f);
        }
    }
    __syncthreads();
    float mh0 = sm_m[0], mh1 = sm_m[1], mh2 = sm_m[2], mh3 = sm_m[3];
    float is0 = sm_is[0], is1 = sm_is[1], is2 = sm_is[2], is3 = sm_is[3];

    // pass 2: chunked alpha + coalesced gather-accumulate
    float acc = 0.f;
    for (int base = 0; base < deg; base += 128) {
        int cn = min(128, deg - base);
        if (tid < cn) {
            int s = g_csr[beg + base + tid];
            float4 av = __ldg((const float4*)(g_asrc + s * NHEAD));
            float l0 = av.x + ad0; l0 = l0 >= 0.f ? l0 : 0.2f * l0;
            float l1 = av.y + ad1; l1 = l1 >= 0.f ? l1 : 0.2f * l1;
            float l2 = av.z + ad2; l2 = l2 >= 0.f ? l2 : 0.2f * l2;
            float l3 = av.w + ad3; l3 = l3 >= 0.f ? l3 : 0.2f * l3;
            float4 al;
            al.x = __expf(l0 - mh0) * is0;
            al.y = __expf(l1 - mh1) * is1;
            al.z = __expf(l2 - mh2) * is2;
            al.w = __expf(l3 - mh3) * is3;
            ((float4*)alpha_s)[tid] = al;
            src_s[tid] = s;
        }
        __syncthreads();
        #pragma unroll 4
        for (int j = 0; j < cn; j++) {
            int s = src_s[j];
            float a = alpha_s[j * 4 + hh];
            acc += a * __ldg(&g_h[(size_t)s * D + tid]);
        }
        __syncthreads();
    }

    // LayerNorm + PReLU + residual
    float v = acc + __ldg(&bias[tid]);
    float s1 = v, s2 = v * v;
    #pragma unroll
    for (int o = 16; o > 0; o >>= 1) {
        s1 += __shfl_xor_sync(0xffffffffu, s1, o);
        s2 += __shfl_xor_sync(0xffffffffu, s2, o);
    }
    if (lane == 0) { rsum[warp] = s1; rsq[warp] = s2; }
    __syncthreads();
    if (tid == 0) {
        float S1 = rsum[0] + rsum[1] + rsum[2] + rsum[3];
        float S2 = rsq[0] + rsq[1] + rsq[2] + rsq[3];
        float mu = S1 * (1.f / 128.f);
        float var = fmaxf(S2 * (1.f / 128.f) - mu * mu, 0.f);
        sm_mu = mu;
        sm_rs = rsqrtf(var + 1e-5f);
    }
    __syncthreads();
    float o = (v - sm_mu) * sm_rs * __ldg(&gamma[tid]) + __ldg(&beta[tid]);
    float pw = __ldg(prelu_w);
    o = o >= 0.f ? o : pw * o;
    out[(size_t)node * D + tid] = o + __ldg(&x[(size_t)node * D + tid]);
}

// ---------------- launch ----------------
extern "C" void kernel_launch(void* const* d_in, const int* in_sizes, int n_in,
                              void* d_out, int out_size) {
    const float* x       = (const float*)d_in[0];
    const void*  ei      = d_in[1];
    const float* W       = (const float*)d_in[2];
    const float* att_src = (const float*)d_in[3];
    const float* att_dst = (const float*)d_in[4];
    const float* bias    = (const float*)d_in[5];
    const float* gamma   = (const float*)d_in[6];
    const float* beta    = (const float*)d_in[7];
    const float* prelu   = (const float*)d_in[8];
    float* out = (float*)d_out;

    int n = in_sizes[0] / D;
    int E = in_sizes[1] / 2;
    int B = (n + 1023) / 1024;

    k_detect<<<1, 1>>>(ei);
    k_zero_deg<<<(n + 255) / 256, 256>>>(n);
    k_extract<<<(E + 255) / 256, 256>>>(ei, E);
    k_scan1<<<B, 1024>>>(n);
    k_scan2<<<1, 1024>>>(B);
    k_scan3<<<B, 1024>>>(n);
    k_scatter<<<(E + 255) / 256, 256>>>(E);
    k_gemm<<<(n + 63) / 64, 256>>>(x, W, att_src, att_dst, n);
    k_node<<<n, 128>>>(x, bias, gamma, beta, prelu, out, n);
}

// round 6
// speedup vs baseline: 1.7897x; 1.3486x over previous
#include <cuda_runtime.h>
#include <math.h>
#include <math_constants.h>

#define NMAX 100000
#define EMAX 1600000
#define D 128
#define NHEAD 4

// ---------------- static scratch (allowed: __device__ globals) ----------------
__device__ float g_h[(size_t)NMAX * D];        // transformed features [N,128]
__device__ float g_asrc[NMAX * NHEAD];         // per-node src attention term
__device__ float g_adst[NMAX * NHEAD];         // per-node dst attention term
__device__ int   g_src[EMAX];
__device__ int   g_dst[EMAX];
__device__ int   g_rank[EMAX];                 // arrival rank among edges sharing dst
__device__ int   g_deg[NMAX];
__device__ int   g_off[NMAX];
__device__ int   g_csr[EMAX];                  // src node per incoming edge, grouped by dst
__device__ int   g_bsum[1024];                 // per-block degree sums for scan
__device__ int   g_is64;

// ---------------- dtype detection for edge_index (int64 vs int32) ----------------
__global__ void k_detect(const void* ei) {
    const unsigned int* w = (const unsigned int*)ei;
    int all0 = 1;
    #pragma unroll
    for (int k = 0; k < 64; k++)
        if (w[2 * k + 1] != 0u) all0 = 0;
    g_is64 = all0;  // values < 2^31 and nonneg -> high word zero iff int64
}

__global__ void k_zero_deg(int n) {
    int i = blockIdx.x * blockDim.x + threadIdx.x;
    if (i < n) g_deg[i] = 0;
}

// extract src/dst, count degree, remember per-edge rank (removes 2nd atomic pass)
__global__ void k_extract(const void* ei, int E) {
    int i = blockIdx.x * blockDim.x + threadIdx.x;
    if (i >= E) return;
    int s, d;
    if (g_is64) {
        const long long* p = (const long long*)ei;
        s = (int)p[i]; d = (int)p[E + i];
    } else {
        const int* p = (const int*)ei;
        s = p[i]; d = p[E + i];
    }
    g_src[i] = s; g_dst[i] = d;
    g_rank[i] = atomicAdd(&g_deg[d], 1);
}

// ---------------- hierarchical exclusive scan of degrees ----------------
__global__ void k_scan1(int n) {
    __shared__ int wsum[32];
    int tid = threadIdx.x;
    int gid = blockIdx.x * 1024 + tid;
    int v = (gid < n) ? g_deg[gid] : 0;
    int lane = tid & 31, wid = tid >> 5;
    int xv = v;
    #pragma unroll
    for (int o = 1; o < 32; o <<= 1) {
        int t = __shfl_up_sync(0xffffffffu, xv, o);
        if (lane >= o) xv += t;
    }
    if (lane == 31) wsum[wid] = xv;
    __syncthreads();
    if (wid == 0) {
        int s = wsum[lane];
        #pragma unroll
        for (int o = 1; o < 32; o <<= 1) {
            int t = __shfl_up_sync(0xffffffffu, s, o);
            if (lane >= o) s += t;
        }
        wsum[lane] = s;
    }
    __syncthreads();
    int incl = xv + (wid ? wsum[wid - 1] : 0);
    if (gid < n) g_off[gid] = incl - v;
    if (tid == 1023) g_bsum[blockIdx.x] = incl;
}

__global__ void k_scan2(int B) {
    __shared__ int wsum[32];
    int tid = threadIdx.x;
    int v = (tid < B) ? g_bsum[tid] : 0;
    int lane = tid & 31, wid = tid >> 5;
    int xv = v;
    #pragma unroll
    for (int o = 1; o < 32; o <<= 1) {
        int t = __shfl_up_sync(0xffffffffu, xv, o);
        if (lane >= o) xv += t;
    }
    if (lane == 31) wsum[wid] = xv;
    __syncthreads();
    if (wid == 0) {
        int s = wsum[lane];
        #pragma unroll
        for (int o = 1; o < 32; o <<= 1) {
            int t = __shfl_up_sync(0xffffffffu, s, o);
            if (lane >= o) s += t;
        }
        wsum[lane] = s;
    }
    __syncthreads();
    int incl = xv + (wid ? wsum[wid - 1] : 0);
    if (tid < B) g_bsum[tid] = incl - v;
}

__global__ void k_scan3(int n) {
    int gid = blockIdx.x * 1024 + threadIdx.x;
    if (gid < n) g_off[gid] += g_bsum[blockIdx.x];
}

// atomic-free scatter using precomputed ranks
__global__ void k_scatter(int E) {
    int i = blockIdx.x * blockDim.x + threadIdx.x;
    if (i >= E) return;
    g_csr[g_off[g_dst[i]] + g_rank[i]] = g_src[i];
}

// ---------------- GEMM: h = x @ W (fp32), fused attention dots ----------------
__global__ void k_gemm(const float* __restrict__ x, const float* __restrict__ W,
                       const float* __restrict__ att_src, const float* __restrict__ att_dst,
                       int n) {
    __shared__ float ws[64 * 128];   // 32KB
    __shared__ float xs[64 * 64];    // 16KB
    int tid = threadIdx.x;
    int r0 = blockIdx.x * 64;
    int w = tid >> 5;
    int l = tid & 31;

    float acc[8][4];
    #pragma unroll
    for (int i = 0; i < 8; i++) { acc[i][0]=0.f; acc[i][1]=0.f; acc[i][2]=0.f; acc[i][3]=0.f; }

    for (int kt = 0; kt < 2; kt++) {
        for (int i = tid; i < 2048; i += 256)
            ((float4*)ws)[i] = ((const float4*)W)[(kt * 64) * 32 + i];
        for (int i = tid; i < 1024; i += 256) {
            int r = i >> 4, c4 = i & 15;
            float4 v = make_float4(0.f, 0.f, 0.f, 0.f);
            if (r0 + r < n) v = ((const float4*)x)[(size_t)(r0 + r) * 32 + kt * 16 + c4];
            ((float4*)xs)[i] = v;
        }
        __syncthreads();
        const float* xrow = xs + w * 8 * 64;
        #pragma unroll 4
        for (int k = 0; k < 64; k++) {
            float4 wv = ((float4*)(ws + k * 128))[l];
            #pragma unroll
            for (int i = 0; i < 8; i++) {
                float xv = xrow[i * 64 + k];
                acc[i][0] += xv * wv.x; acc[i][1] += xv * wv.y;
                acc[i][2] += xv * wv.z; acc[i][3] += xv * wv.w;
            }
        }
        __syncthreads();
    }

    float4 asv = __ldg(((const float4*)att_src) + l);
    float4 adv = __ldg(((const float4*)att_dst) + l);
    int head = l >> 3;
    #pragma unroll
    for (int i = 0; i < 8; i++) {
        int r = r0 + w * 8 + i;
        if (r < n) {
            ((float4*)(g_h + (size_t)r * D))[l] =
                make_float4(acc[i][0], acc[i][1], acc[i][2], acc[i][3]);
            float ps = acc[i][0]*asv.x + acc[i][1]*asv.y + acc[i][2]*asv.z + acc[i][3]*asv.w;
            float pd = acc[i][0]*adv.x + acc[i][1]*adv.y + acc[i][2]*adv.z + acc[i][3]*adv.w;
            #pragma unroll
            for (int o = 1; o < 8; o <<= 1) {
                ps += __shfl_xor_sync(0xffffffffu, ps, o);
                pd += __shfl_xor_sync(0xffffffffu, pd, o);
            }
            if ((l & 7) == 0) {
                g_asrc[r * NHEAD + head] = ps;
                g_adst[r * NHEAD + head] = pd;
            }
        }
    }
}

// ---------------- fused per-node (SINGLE PASS): unnormalized softmax gather
//                  + normalize + LN + PReLU + residual ----------------
// Safe without max-subtraction: logits here are O(10), exp() far from overflow,
// and alpha = exp(e)/sum exp(e) is identical with or without the max shift.
__global__ void k_node(const float* __restrict__ x, const float* __restrict__ bias,
                       const float* __restrict__ gamma, const float* __restrict__ beta,
                       const float* __restrict__ prelu_w, float* __restrict__ out, int n) {
    int node = blockIdx.x;
    int tid = threadIdx.x;              // 128 threads = 128 channels
    int lane = tid & 31, warp = tid >> 5;
    int hh = tid >> 5;                  // head of this channel

    __shared__ float alpha_s[128 * 4];  // unnormalized exp weights per chunk
    __shared__ int   src_s[128];
    __shared__ float adsh[4];
    __shared__ float redd[4][4];        // [warp][head] partial denominators
    __shared__ float sm_inv[4];
    __shared__ float rsum[4], rsq[4];
    __shared__ float sm_mu, sm_rs;

    int beg = g_off[node];
    int deg = g_deg[node];

    if (tid < 4) adsh[tid] = g_adst[node * NHEAD + tid];
    __syncthreads();
    float ad0 = adsh[0], ad1 = adsh[1], ad2 = adsh[2], ad3 = adsh[3];

    float den0 = 0.f, den1 = 0.f, den2 = 0.f, den3 = 0.f;
    float acc = 0.f;

    for (int base = 0; base < deg; base += 128) {
        int cn = min(128, deg - base);
        if (tid < cn) {
            int s = g_csr[beg + base + tid];
            float4 av = __ldg((const float4*)(g_asrc + s * NHEAD));
            float l0 = av.x + ad0; l0 = l0 >= 0.f ? l0 : 0.2f * l0;
            float l1 = av.y + ad1; l1 = l1 >= 0.f ? l1 : 0.2f * l1;
            float l2 = av.z + ad2; l2 = l2 >= 0.f ? l2 : 0.2f * l2;
            float l3 = av.w + ad3; l3 = l3 >= 0.f ? l3 : 0.2f * l3;
            float4 wv;
            wv.x = __expf(l0); wv.y = __expf(l1);
            wv.z = __expf(l2); wv.w = __expf(l3);
            ((float4*)alpha_s)[tid] = wv;
            src_s[tid] = s;
            den0 += wv.x; den1 += wv.y; den2 += wv.z; den3 += wv.w;
        }
        __syncthreads();
        #pragma unroll 8
        for (int j = 0; j < cn; j++) {
            int s = src_s[j];                          // smem broadcast
            float a = alpha_s[j * 4 + hh];             // smem broadcast
            acc += a * __ldg(&g_h[(size_t)s * D + tid]);  // coalesced, L2-served
        }
        __syncthreads();
    }

    // block-reduce the 4 per-head denominators
    #pragma unroll
    for (int o = 16; o > 0; o >>= 1) {
        den0 += __shfl_xor_sync(0xffffffffu, den0, o);
        den1 += __shfl_xor_sync(0xffffffffu, den1, o);
        den2 += __shfl_xor_sync(0xffffffffu, den2, o);
        den3 += __shfl_xor_sync(0xffffffffu, den3, o);
    }
    if (lane == 0) {
        redd[warp][0] = den0; redd[warp][1] = den1;
        redd[warp][2] = den2; redd[warp][3] = den3;
    }
    __syncthreads();
    if (tid < 4) {
        float s = redd[0][tid] + redd[1][tid] + redd[2][tid] + redd[3][tid];
        sm_inv[tid] = (s > 0.f) ? (1.f / s) : 0.f;   // deg==0 -> output 0 (matches ref)
    }
    __syncthreads();

    // LayerNorm + PReLU + residual
    float v = acc * sm_inv[hh] + __ldg(&bias[tid]);
    float s1 = v, s2 = v * v;
    #pragma unroll
    for (int o = 16; o > 0; o >>= 1) {
        s1 += __shfl_xor_sync(0xffffffffu, s1, o);
        s2 += __shfl_xor_sync(0xffffffffu, s2, o);
    }
    if (lane == 0) { rsum[warp] = s1; rsq[warp] = s2; }
    __syncthreads();
    if (tid == 0) {
        float S1 = rsum[0] + rsum[1] + rsum[2] + rsum[3];
        float S2 = rsq[0] + rsq[1] + rsq[2] + rsq[3];
        float mu = S1 * (1.f / 128.f);
        float var = fmaxf(S2 * (1.f / 128.f) - mu * mu, 0.f);
        sm_mu = mu;
        sm_rs = rsqrtf(var + 1e-5f);
    }
    __syncthreads();
    float o = (v - sm_mu) * sm_rs * __ldg(&gamma[tid]) + __ldg(&beta[tid]);
    float pw = __ldg(prelu_w);
    o = o >= 0.f ? o : pw * o;
    out[(size_t)node * D + tid] = o + __ldg(&x[(size_t)node * D + tid]);
}

// ---------------- launch ----------------
extern "C" void kernel_launch(void* const* d_in, const int* in_sizes, int n_in,
                              void* d_out, int out_size) {
    const float* x       = (const float*)d_in[0];
    const void*  ei      = d_in[1];
    const float* W       = (const float*)d_in[2];
    const float* att_src = (const float*)d_in[3];
    const float* att_dst = (const float*)d_in[4];
    const float* bias    = (const float*)d_in[5];
    const float* gamma   = (const float*)d_in[6];
    const float* beta    = (const float*)d_in[7];
    const float* prelu   = (const float*)d_in[8];
    float* out = (float*)d_out;

    int n = in_sizes[0] / D;
    int E = in_sizes[1] / 2;
    int B = (n + 1023) / 1024;

    k_detect<<<1, 1>>>(ei);
    k_zero_deg<<<(n + 255) / 256, 256>>>(n);
    k_extract<<<(E + 255) / 256, 256>>>(ei, E);
    k_scan1<<<B, 1024>>>(n);
    k_scan2<<<1, 1024>>>(B);
    k_scan3<<<B, 1024>>>(n);
    k_scatter<<<(E + 255) / 256, 256>>>(E);
    k_gemm<<<(n + 63) / 64, 256>>>(x, W, att_src, att_dst, n);
    k_node<<<n, 128>>>(x, bias, gamma, beta, prelu, out, n);
}